// round 4
// baseline (speedup 1.0000x reference)
#include <cuda_runtime.h>
#include <cstdint>

#define NB 8
#define LQ 8192
#define SK 8192
#define HH 8
#define DD 32
#define NH (NB*HH)
#define EPSV 1e-6f

// pass1
#define CHUNKS 8
#define SROWS (SK / CHUNKS)   // 1024 s-rows per block
#define TS 32                 // smem tile rows
#define TILES (SROWS / TS)    // 32

// pass2
#define P2_THREADS 512
#define P2_L 64                 // l rows per block
#define P2_ROWS (P2_L * HH)     // 512 (l,h) rows
#define QSTRIDE 36              // padded floats per q row in smem
#define KVSTRIDE 1028           // per-head KV stride in floats (pad vs 1024)
#define KSSTRIDE 33
#define P2_SMEM_FLOATS (P2_ROWS*QSTRIDE + HH*KVSTRIDE + HH*KSSTRIDE)
#define P2_SMEM_BYTES (P2_SMEM_FLOATS * 4)

// Scratch (device globals: no allocation allowed)
__device__ __align__(16) float g_KV[NH * DD * DD];   // [nh][d][v]
__device__ __align__(16) float g_Ksum[NH * DD];      // [nh][d]

__device__ __forceinline__ float elu1(float x) {
    return x > 0.f ? x + 1.f : __expf(x);
}

__device__ __forceinline__ void fma2(unsigned long long &acc,
                                     unsigned long long a,
                                     unsigned long long b) {
    asm("fma.rn.f32x2 %0, %1, %2, %0;" : "+l"(acc) : "l"(a), "l"(b));
}
__device__ __forceinline__ unsigned long long pk(float x, float y) {
    unsigned long long r;
    asm("mov.b64 %0, {%1,%2};" : "=l"(r) : "f"(x), "f"(y));
    return r;
}
__device__ __forceinline__ float2 upk(unsigned long long v) {
    float2 r;
    asm("mov.b64 {%0,%1}, %2;" : "=f"(r.x), "=f"(r.y) : "l"(v));
    return r;
}

__global__ void zero_kernel() {
    int i = blockIdx.x * blockDim.x + threadIdx.x;
    if (i < NH * DD * DD) g_KV[i] = 0.f;
    if (i < NH * DD)      g_Ksum[i] = 0.f;
}

// ---------------------------------------------------------------------------
// Pass 1: KV[nh] += sum_s outer(eluK_s, v_s);  Ksum[nh] += sum_s eluK_s
// grid (CHUNKS, NH), 256 threads = 8 warps, double-buffered 32-row tiles.
// ---------------------------------------------------------------------------
__global__ __launch_bounds__(256, 4) void pass1(const float* __restrict__ keys,
                                                const float* __restrict__ values) {
    // layout: kbuf0 [0,2048) kbuf1 [2048,4096) vbuf0 [4096,5120) vbuf1 [5120,6144)
    // overlays after mainloop: sRed = sm[0..4096), sKsum = sm[4096..5120)
    __shared__ __align__(16) float sm[6144];

    const int nh = blockIdx.y;
    const int n = nh / HH, h = nh % HH;
    const int tid = threadIdx.x;
    const int w = tid >> 5, lane = tid & 31;
    const int d0 = (lane >> 2) * 4;   // 0,4,...,28
    const int v0 = (lane & 3) * 8;    // 0,8,16,24
    const int r = tid >> 3;           // 0..31  (row loaded by this thread)
    const int c4 = (tid & 7) * 4;     // 0..28  (col group)

    unsigned long long acc[4][4];
#pragma unroll
    for (int i = 0; i < 4; ++i)
#pragma unroll
        for (int j = 0; j < 4; ++j) acc[i][j] = 0ull;
    float4 ksacc = make_float4(0.f, 0.f, 0.f, 0.f);

    const size_t base = ((size_t)n * SK * HH + h) * DD;
    const int rs = HH * DD;   // 256 floats between s-rows
    const int s_begin = blockIdx.x * SROWS;

    const float* kptr = keys   + base + (size_t)(s_begin + r) * rs + c4;
    const float* vptr = values + base + (size_t)(s_begin + r) * rs + c4;

    float4 kq = *(const float4*)kptr;
    float4 vq = *(const float4*)vptr;

    for (int t = 0; t < TILES; ++t) {
        float* kd = (t & 1) ? (sm + 2048) : sm;
        float* vd = (t & 1) ? (sm + 5120) : (sm + 4096);

        const float k0 = elu1(kq.x), k1 = elu1(kq.y), k2 = elu1(kq.z), k3 = elu1(kq.w);
        ksacc.x += k0; ksacc.y += k1; ksacc.z += k2; ksacc.w += k3;
        *(float4*)&kd[r * 64 + c4 * 2]     = make_float4(k0, k0, k1, k1);
        *(float4*)&kd[r * 64 + c4 * 2 + 4] = make_float4(k2, k2, k3, k3);
        *(float4*)&vd[r * 32 + c4] = vq;

        if (t + 1 < TILES) {   // prefetch next tile; lands during compute
            kq = *(const float4*)(kptr + (size_t)(t + 1) * TS * rs);
            vq = *(const float4*)(vptr + (size_t)(t + 1) * TS * rs);
        }
        __syncthreads();

        const float* kd2 = kd;
        const float* vd2 = vd;
#pragma unroll
        for (int rr = 0; rr < 4; ++rr) {
            const int s = w * 4 + rr;
            const ulonglong2 ka = *(const ulonglong2*)&kd2[s * 64 + d0 * 2];
            const ulonglong2 kb = *(const ulonglong2*)&kd2[s * 64 + d0 * 2 + 4];
            const ulonglong2 va = *(const ulonglong2*)&vd2[s * 32 + v0];
            const ulonglong2 vb = *(const ulonglong2*)&vd2[s * 32 + v0 + 4];
            const unsigned long long kk[4] = {ka.x, ka.y, kb.x, kb.y};
            const unsigned long long vv[4] = {va.x, va.y, vb.x, vb.y};
#pragma unroll
            for (int i = 0; i < 4; ++i)
#pragma unroll
                for (int j = 0; j < 4; ++j) fma2(acc[i][j], kk[i], vv[j]);
        }
        // no trailing sync needed: next STS targets the other buffer, whose
        // last readers finished before the sync we just passed.
    }
    __syncthreads();

    // reduce the 8 warp replicas in smem (overlay), then atomicAdd into g_KV
    float (*sRed)[512] = (float (*)[512])sm;
    for (int half = 0; half < 2; ++half) {
        if ((d0 >> 4) == half) {
            const int dl = d0 & 15;
#pragma unroll
            for (int i = 0; i < 4; ++i) {
                float* dst = &sRed[w][(dl + i) * DD + v0];
                *(ulonglong2*)dst       = make_ulonglong2(acc[i][0], acc[i][1]);
                *(ulonglong2*)(dst + 4) = make_ulonglong2(acc[i][2], acc[i][3]);
            }
        }
        __syncthreads();
        for (int e = tid; e < 512; e += 256) {
            float ssum = 0.f;
#pragma unroll
            for (int ww = 0; ww < 8; ++ww) ssum += sRed[ww][e];
            const int d = half * 16 + e / DD;
            const int v = e % DD;
            atomicAdd(&g_KV[(nh * DD + d) * DD + v], ssum);
        }
        __syncthreads();
    }

    // Ksum reduction (overlay at sm+4096)
    float4* sKsum = (float4*)(sm + 4096);
    sKsum[tid] = ksacc;
    __syncthreads();
    if (tid < DD) {
        const int cgrp = tid >> 2;
        const int comp = tid & 3;
        float ssum = 0.f;
        for (int k = 0; k < 32; ++k) {
            const float4 vk = sKsum[cgrp + 8 * k];
            ssum += (comp == 0) ? vk.x : (comp == 1) ? vk.y : (comp == 2) ? vk.z : vk.w;
        }
        atomicAdd(&g_Ksum[nh * DD + tid], ssum);
    }
}

// ---------------------------------------------------------------------------
// Pass 2: out[l,h,:] = (eluQ @ KV_h) / (eluQ . Ksum_h + eps)
// grid (LQ/P2_L, NB), 512 threads. Block covers 64 l's x all 8 heads
// = 512 contiguous (l,h) rows. Q and out staged through padded smem so all
// gmem traffic is coalesced float4 streams. KV broadcast from padded smem.
// ---------------------------------------------------------------------------
__global__ __launch_bounds__(P2_THREADS, 2) void pass2(const float* __restrict__ queries,
                                                       float* __restrict__ out) {
    extern __shared__ __align__(16) float dyn[];
    float* sQ  = dyn;                                    // 512 rows x stride 36
    float* sKV = dyn + P2_ROWS * QSTRIDE;                // 8 heads x stride 1028
    float* sKs = dyn + P2_ROWS * QSTRIDE + HH * KVSTRIDE;

    const int n  = blockIdx.y;
    const int l0 = blockIdx.x * P2_L;
    const int tid = threadIdx.x;

    // load KV for all 8 heads of this n (contiguous 8192 floats), padded
    const float* kvsrc = &g_KV[(size_t)(n * HH) * DD * DD];
#pragma unroll
    for (int i = 0; i < 4; ++i) {
        const int f4 = tid + P2_THREADS * i;   // 0..2047
        const int hh = f4 >> 8;                // 256 float4 per head
        const int off = (f4 & 255) * 4;
        *(float4*)&sKV[hh * KVSTRIDE + off] = *(const float4*)(kvsrc + f4 * 4);
    }
    if (tid < HH * DD) {
        const int hh = tid >> 5, d = tid & 31;
        sKs[hh * KSSTRIDE + d] = g_Ksum[(n * HH + hh) * DD + d];
    }

    // stage Q with elu applied: fully coalesced gmem reads
    const float* qsrc = queries + ((size_t)n * LQ + l0) * (HH * DD);
#pragma unroll
    for (int i = 0; i < 8; ++i) {
        const int f4 = tid + P2_THREADS * i;   // 0..4095
        const float4 qv = *(const float4*)(qsrc + (size_t)f4 * 4);
        const int row = f4 >> 3, cc = (f4 & 7) * 4;
        *(float4*)&sQ[row * QSTRIDE + cc] =
            make_float4(elu1(qv.x), elu1(qv.y), elu1(qv.z), elu1(qv.w));
    }
    __syncthreads();

    // thread -> its (l,h) row
    const int h = tid & 7;
    const float* qrow = &sQ[tid * QSTRIDE];
    const float* kvh  = &sKV[h * KVSTRIDE];
    const float* ksh  = &sKs[h * KSSTRIDE];

    unsigned long long acc[16];
#pragma unroll
    for (int p = 0; p < 16; ++p) acc[p] = 0ull;
    float z = EPSV;

#pragma unroll
    for (int dd4 = 0; dd4 < DD; dd4 += 4) {
        const float4 q4 = *(const float4*)(qrow + dd4);
        const float qs[4] = {q4.x, q4.y, q4.z, q4.w};
#pragma unroll
        for (int j = 0; j < 4; ++j) {
            const int d = dd4 + j;
            z += qs[j] * ksh[d];
            const unsigned long long qd = pk(qs[j], qs[j]);
            const ulonglong2* kr = (const ulonglong2*)(kvh + d * DD);
#pragma unroll
            for (int p = 0; p < 8; ++p) {
                const ulonglong2 kv2 = kr[p];
                fma2(acc[2 * p],     qd, kv2.x);
                fma2(acc[2 * p + 1], qd, kv2.y);
            }
        }
    }

    const float inv = 1.0f / z;
    __syncthreads();            // done reading sQ; reuse it as out staging
#pragma unroll
    for (int t2 = 0; t2 < 8; ++t2) {
        const float2 a = upk(acc[2 * t2]);
        const float2 b = upk(acc[2 * t2 + 1]);
        *(float4*)&sQ[tid * QSTRIDE + t2 * 4] =
            make_float4(a.x * inv, a.y * inv, b.x * inv, b.y * inv);
    }
    __syncthreads();

    // coalesced output
    float* orow = out + ((size_t)n * LQ + l0) * (HH * DD);
#pragma unroll
    for (int i = 0; i < 8; ++i) {
        const int f4 = tid + P2_THREADS * i;
        const int row = f4 >> 3, cc = (f4 & 7) * 4;
        *(float4*)(orow + (size_t)f4 * 4) = *(const float4*)&sQ[row * QSTRIDE + cc];
    }
}

extern "C" void kernel_launch(void* const* d_in, const int* in_sizes, int n_in,
                              void* d_out, int out_size) {
    (void)in_sizes; (void)n_in; (void)out_size;
    const float* q = (const float*)d_in[0];
    const float* k = (const float*)d_in[1];
    const float* v = (const float*)d_in[2];
    float* out = (float*)d_out;

    zero_kernel<<<(NH * DD * DD + 255) / 256, 256>>>();
    pass1<<<dim3(CHUNKS, NH), 256>>>(k, v);
    cudaFuncSetAttribute(pass2, cudaFuncAttributeMaxDynamicSharedMemorySize, P2_SMEM_BYTES);
    pass2<<<dim3(LQ / P2_L, NB), P2_THREADS, P2_SMEM_BYTES>>>(q, out);
}

// round 6
// speedup vs baseline: 1.0374x; 1.0374x over previous
#include <cuda_runtime.h>
#include <cstdint>

#define NB 8
#define LQ 8192
#define SK 8192
#define HH 8
#define DD 32
#define NH (NB*HH)
#define EPSV 1e-6f

// pass1
#define CHUNKS 16
#define SROWS (SK / CHUNKS)   // 512 s-rows per block
#define TS 32                 // tile rows
#define TILES (SROWS / TS)    // 16

// pass2
#define P2_THREADS 256
#define P2_L 32                     // l rows per block
#define P2_ROWS (P2_L * HH)         // 256 (l,h) rows
#define QDSTRIDE 72                 // dup'd q row stride in floats (64 data + pad)
#define KSSTRIDE 33
#define P2_SMEM_FLOATS (P2_ROWS*QDSTRIDE + HH*KSSTRIDE + P2_ROWS)
#define P2_SMEM_BYTES (P2_SMEM_FLOATS * 4)

// Scratch (device globals: no allocation allowed)
__device__ __align__(16) float g_KV[NH * DD * DD];   // [nh][d][v]
__device__ __align__(16) float g_Ksum[NH * DD];      // [nh][d]

__device__ __forceinline__ float elu1(float x) {
    return x > 0.f ? x + 1.f : __expf(x);
}

__device__ __forceinline__ void fma2(unsigned long long &acc,
                                     unsigned long long a,
                                     unsigned long long b) {
    asm("fma.rn.f32x2 %0, %1, %2, %0;" : "+l"(acc) : "l"(a), "l"(b));
}
__device__ __forceinline__ unsigned long long pk(float x, float y) {
    unsigned long long r;
    asm("mov.b64 %0, {%1,%2};" : "=l"(r) : "f"(x), "f"(y));
    return r;
}
__device__ __forceinline__ float2 upk(unsigned long long v) {
    float2 r;
    asm("mov.b64 {%0,%1}, %2;" : "=f"(r.x), "=f"(r.y) : "l"(v));
    return r;
}

__global__ void zero_kernel() {
    int i = blockIdx.x * blockDim.x + threadIdx.x;
    if (i < NH * DD * DD) g_KV[i] = 0.f;
    if (i < NH * DD)      g_Ksum[i] = 0.f;
}

// ---------------------------------------------------------------------------
// Pass 1: KV[nh] += sum_s outer(eluK_s, v_s);  Ksum[nh] += sum_s eluK_s
// grid (CHUNKS, NH), 256 threads = 8 warps. Each HALF-warp holds a full
// 32x32 KV replica in registers: lane owns v-pair vp=lane&15, acc[d] u64.
// K read as dup-pair broadcast LDS.128 (crossbar-free), V as LDS.64.
// ---------------------------------------------------------------------------
__global__ __launch_bounds__(256, 2) void pass1(const float* __restrict__ keys,
                                                const float* __restrict__ values) {
    // [0,2048) kd0 | [2048,4096) kd1 | [4096,5120) v0 | [5120,6144) v1
    // overlay after mainloop: sRed = sm[0..8192) as [8][1024]
    __shared__ __align__(16) float sm[8192];
    __shared__ __align__(16) float4 sKsum[256];

    const int nh = blockIdx.y;
    const int n = nh / HH, h = nh % HH;
    const int tid = threadIdx.x;
    const int w = tid >> 5, lane = tid & 31;
    const int half = lane >> 4;       // 0/1: which s-row of the pair
    const int vp = lane & 15;         // v-pair index: v = 2*vp, 2*vp+1
    const int r = tid >> 3;           // loader row 0..31
    const int c4 = (tid & 7) * 4;     // loader col group

    unsigned long long acc[DD];
#pragma unroll
    for (int d = 0; d < DD; ++d) acc[d] = 0ull;
    float4 ksacc = make_float4(0.f, 0.f, 0.f, 0.f);

    const size_t base = ((size_t)n * SK * HH + h) * DD;
    const int rs = HH * DD;   // 256 floats between s-rows
    const int s_begin = blockIdx.x * SROWS;

    const float* kptr = keys   + base + (size_t)(s_begin + r) * rs + c4;
    const float* vptr = values + base + (size_t)(s_begin + r) * rs + c4;

    float4 kq = *(const float4*)kptr;
    float4 vq = *(const float4*)vptr;

    for (int t = 0; t < TILES; ++t) {
        float* kd = sm + (t & 1) * 2048;          // 32 rows x 64 (dup pairs)
        float* vd = sm + 4096 + (t & 1) * 1024;   // 32 rows x 32

        const float k0 = elu1(kq.x), k1 = elu1(kq.y), k2 = elu1(kq.z), k3 = elu1(kq.w);
        ksacc.x += k0; ksacc.y += k1; ksacc.z += k2; ksacc.w += k3;
        *(float4*)&kd[r * 64 + c4 * 2]     = make_float4(k0, k0, k1, k1);
        *(float4*)&kd[r * 64 + c4 * 2 + 4] = make_float4(k2, k2, k3, k3);
        *(float4*)&vd[r * 32 + c4] = vq;

        if (t + 1 < TILES) {
            kq = *(const float4*)(kptr + (size_t)(t + 1) * TS * rs);
            vq = *(const float4*)(vptr + (size_t)(t + 1) * TS * rs);
        }
        __syncthreads();

#pragma unroll
        for (int step = 0; step < 2; ++step) {
            const int row = w * 4 + step * 2 + half;
            const unsigned long long vv = *(const unsigned long long*)&vd[row * 32 + vp * 2];
            const ulonglong2* krow = (const ulonglong2*)&kd[row * 64];
#pragma unroll
            for (int j = 0; j < 16; ++j) {
                const ulonglong2 kk = krow[j];   // (k_{2j},k_{2j}),(k_{2j+1},k_{2j+1})
                fma2(acc[2 * j],     kk.x, vv);
                fma2(acc[2 * j + 1], kk.y, vv);
            }
        }
        // next iteration stores to the other buffer; safe without trailing sync
    }
    __syncthreads();

    // combine the two half-warp replicas: element (d,vp) lives at lanes vp, vp+16
#pragma unroll
    for (int d = 0; d < DD; ++d) {
        float2 a = upk(acc[d]);
        a.x += __shfl_down_sync(0xffffffffu, a.x, 16);
        a.y += __shfl_down_sync(0xffffffffu, a.y, 16);
        acc[d] = pk(a.x, a.y);
    }

    // 8 warp replicas -> smem -> atomicAdd
    if (half == 0) {
#pragma unroll
        for (int d = 0; d < DD; ++d)
            *(unsigned long long*)&sm[w * 1024 + d * 32 + vp * 2] = acc[d];
    }
    __syncthreads();
    {
        float4 ssum = make_float4(0.f, 0.f, 0.f, 0.f);
#pragma unroll
        for (int ww = 0; ww < 8; ++ww) {
            const float4 vv = *(const float4*)&sm[ww * 1024 + tid * 4];
            ssum.x += vv.x; ssum.y += vv.y; ssum.z += vv.z; ssum.w += vv.w;
        }
        float* dst = &g_KV[nh * 1024 + tid * 4];
        atomicAdd(dst + 0, ssum.x);
        atomicAdd(dst + 1, ssum.y);
        atomicAdd(dst + 2, ssum.z);
        atomicAdd(dst + 3, ssum.w);
    }

    // Ksum reduction
    sKsum[tid] = ksacc;
    __syncthreads();
    if (tid < DD) {
        const int cgrp = tid >> 2;
        const int comp = tid & 3;
        float ssum = 0.f;
        for (int k = 0; k < 32; ++k) {
            const float4 vk = sKsum[cgrp + 8 * k];
            ssum += (comp == 0) ? vk.x : (comp == 1) ? vk.y : (comp == 2) ? vk.z : vk.w;
        }
        atomicAdd(&g_Ksum[nh * DD + tid], ssum);
    }
}

// ---------------------------------------------------------------------------
// Pass 2: out[l,h,:] = (eluQ @ KV_h) / (eluQ . Ksum_h + eps)
// grid (LQ/P2_L, NB), 256 threads = 8 warps; warp w owns head h=w and keeps
// the full KV_h in registers (u64 v-pair per lane, replicated per half-warp).
// Q staged dup-packed in smem; rows consumed via broadcast LDS.128.
// ---------------------------------------------------------------------------
__global__ __launch_bounds__(P2_THREADS, 2) void pass2(const float* __restrict__ queries,
                                                       float* __restrict__ out) {
    extern __shared__ __align__(16) float dyn[];
    float* sQd  = dyn;                              // 256 rows x 72 (dup pairs + pad)
    float* sKs  = dyn + P2_ROWS * QDSTRIDE;         // 8 x 33
    float* sInv = sKs + HH * KSSTRIDE;              // 256

    const int n  = blockIdx.y;
    const int l0 = blockIdx.x * P2_L;
    const int tid = threadIdx.x;
    const int w = tid >> 5, lane = tid & 31;
    const int half = lane >> 4;
    const int vp = lane & 15;

    // KV_h -> registers (L2-resident; issued first to overlap with staging)
    unsigned long long kvr[DD];
    {
        const float* kvh = &g_KV[(size_t)(n * HH + w) * DD * DD];
#pragma unroll
        for (int d = 0; d < DD; ++d)
            kvr[d] = *(const unsigned long long*)(kvh + d * DD + vp * 2);
    }

    // stage Q dup-packed with elu applied (coalesced gmem reads)
    const float* qsrc = queries + ((size_t)n * LQ + l0) * (HH * DD);
#pragma unroll
    for (int i = 0; i < 8; ++i) {
        const int f4 = tid + P2_THREADS * i;        // 0..2047
        const float4 qv = *(const float4*)(qsrc + (size_t)f4 * 4);
        const float e0 = elu1(qv.x), e1 = elu1(qv.y), e2 = elu1(qv.z), e3 = elu1(qv.w);
        const int row = f4 >> 3, cc = (f4 & 7) * 4;
        *(float4*)&sQd[row * QDSTRIDE + cc * 2]     = make_float4(e0, e0, e1, e1);
        *(float4*)&sQd[row * QDSTRIDE + cc * 2 + 4] = make_float4(e2, e2, e3, e3);
    }
    {
        const int h2 = tid >> 5, d = tid & 31;      // 256 threads = all (h,d)
        sKs[h2 * KSSTRIDE + d] = g_Ksum[(n * HH + h2) * DD + d];
    }
    __syncthreads();

    // z per row: thread tid owns row tid (l = tid>>3, h = tid&7)
    {
        const int h2 = tid & 7;
        const float* qrow = &sQd[tid * QDSTRIDE];
        const float* ksh = &sKs[h2 * KSSTRIDE];
        float z = EPSV;
#pragma unroll
        for (int j = 0; j < 16; ++j) {
            const float4 qq = *(const float4*)(qrow + j * 4);  // (q2j,q2j,q2j+1,q2j+1)
            z += qq.x * ksh[2 * j] + qq.z * ksh[2 * j + 1];
        }
        sInv[tid] = 1.0f / z;
    }
    __syncthreads();

    // main: warp w = head w; per step the two half-warps do rows l=2s, 2s+1
#pragma unroll 4
    for (int step = 0; step < P2_L / 2; ++step) {
        const int row = (step * 2 + half) * HH + w;
        const ulonglong2* qrow = (const ulonglong2*)&sQd[row * QDSTRIDE];
        unsigned long long a0 = 0ull, a1 = 0ull;
#pragma unroll
        for (int j = 0; j < 8; ++j) {
            const ulonglong2 q01 = qrow[2 * j];
            const ulonglong2 q23 = qrow[2 * j + 1];
            fma2(a0, q01.x, kvr[4 * j]);
            fma2(a1, q01.y, kvr[4 * j + 1]);
            fma2(a0, q23.x, kvr[4 * j + 2]);
            fma2(a1, q23.y, kvr[4 * j + 3]);
        }
        const float inv = sInv[row];
        const float2 r0 = upk(a0);
        const float2 r1 = upk(a1);
        float* orow = out + ((size_t)n * LQ + l0) * (HH * DD) + (size_t)row * DD + vp * 2;
        *(float2*)orow = make_float2((r0.x + r1.x) * inv, (r0.y + r1.y) * inv);
    }
}

extern "C" void kernel_launch(void* const* d_in, const int* in_sizes, int n_in,
                              void* d_out, int out_size) {
    (void)in_sizes; (void)n_in; (void)out_size;
    const float* q = (const float*)d_in[0];
    const float* k = (const float*)d_in[1];
    const float* v = (const float*)d_in[2];
    float* out = (float*)d_out;

    zero_kernel<<<(NH * DD * DD + 255) / 256, 256>>>();
    pass1<<<dim3(CHUNKS, NH), 256>>>(k, v);
    cudaFuncSetAttribute(pass2, cudaFuncAttributeMaxDynamicSharedMemorySize, P2_SMEM_BYTES);
    pass2<<<dim3(LQ / P2_L, NB), P2_THREADS, P2_SMEM_BYTES>>>(q, out);
}